// round 4
// baseline (speedup 1.0000x reference)
#include <cuda_runtime.h>
#include <cstdint>

// Problem constants
#define SEQ_L   2048      // SEQ_LEN - 1
#define NFEAT   11
#define NBATCH  1024
#define TPB     256

// Mask rows as 8-bit masks, bit i = mask element i.
//  0:[0,1,0,0,0,0,0,0]=0x02  1:[0,1,1,0,0,0,0,0]=0x06  2:[0,0,0,0,1,0,0,0]=0x10
//  3:[0,0,0,1,1,1,1,1]=0xF8  7:[0,0,0,0,0,0,0,1]=0x80  4,5,6,8 = 0
#define B_FULL  0xF8u
#define B_NO_TS 0x20u
#define B_NO_TP 0x40u

// -------- scratch (static device memory; no allocation) --------
__device__ unsigned int g_sv32[NBATCH * SEQ_L / 4];  // compact gt bytes, 2 MB
__device__ int g_f5[NBATCH * 2];                     // first idx of 5 per half
__device__ int g_f6[NBATCH * 2];                     // first idx of 6 per half

__device__ __forceinline__ unsigned base_bits(int v) {
    unsigned b = 0u;
    b = (v == 0) ? 0x02u : b;
    b = (v == 1) ? 0x06u : b;
    b = (v == 2) ? 0x10u : b;
    b = (v == 3) ? 0xF8u : b;
    b = (v == 7) ? 0x80u : b;
    return b;
}

__device__ __forceinline__ uint4 expand4(unsigned nib) {
    uint4 r;
    r.x = (nib & 1u) ? 0x3F800000u : 0u;
    r.y = (nib & 2u) ? 0x3F800000u : 0u;
    r.z = (nib & 4u) ? 0x3F800000u : 0u;
    r.w = (nib & 8u) ? 0x3F800000u : 0u;
    return r;
}

// ================= Kernel A: gather + per-half first-occurrence =============
// grid = NBATCH*2, one CTA per (batch, half). Each thread handles 4
// consecutive t, packs 4 gt bytes into one coalesced uint32 store.
__global__ __launch_bounds__(TPB)
void gather_kernel(const int* __restrict__ in) {
    const int cta = blockIdx.x;
    const int b   = cta >> 1;
    const int h   = cta & 1;
    const int tid = threadIdx.x;

    const int t0 = h * (SEQ_L / 2) + tid * 4;   // 4 consecutive elements
    const int* p = in + (size_t)b * SEQ_L * NFEAT + (size_t)t0 * NFEAT;

    int f5 = SEQ_L, f6 = SEQ_L;
    unsigned packed = 0;

#pragma unroll
    for (int j = 0; j < 4; ++j) {
        int v = __ldcs(p + j * NFEAT);
        v = v < 0 ? 0 : (v > 8 ? 8 : v);
        packed |= (unsigned)v << (j * 8);
        const int t = t0 + j;
        if (v == 5) f5 = min(f5, t);
        if (v == 6) f6 = min(f6, t);
    }
    g_sv32[((size_t)b * SEQ_L >> 2) + (h * (SEQ_L / 8)) + tid] = packed;

    // reduce first occurrence over the CTA
#pragma unroll
    for (int off = 16; off > 0; off >>= 1) {
        f5 = min(f5, __shfl_down_sync(0xFFFFFFFFu, f5, off));
        f6 = min(f6, __shfl_down_sync(0xFFFFFFFFu, f6, off));
    }
    __shared__ int s5[TPB / 32];
    __shared__ int s6[TPB / 32];
    const int lane = tid & 31;
    const int wid  = tid >> 5;
    if (lane == 0) { s5[wid] = f5; s6[wid] = f6; }
    __syncthreads();
    if (tid == 0) {
        int F5 = SEQ_L, F6 = SEQ_L;
#pragma unroll
        for (int i = 0; i < TPB / 32; ++i) {
            F5 = min(F5, s5[i]);
            F6 = min(F6, s6[i]);
        }
        g_f5[cta] = F5;
        g_f6[cta] = F6;
    }
}

// ================= Kernel B: expand to float masks, streaming stores ========
// grid = NBATCH*4, one CTA per 512-element tile. 1024 uint4 slots per tile,
// 4 per thread, warp stores 512 contiguous bytes.
__global__ __launch_bounds__(TPB)
void expand_kernel(uint4* __restrict__ out) {
    const int cta = blockIdx.x;
    const int b   = cta >> 2;
    const int p   = cta & 3;
    const int tid = threadIdx.x;

    const int F5 = min(g_f5[b * 2], g_f5[b * 2 + 1]);
    const int F6 = min(g_f6[b * 2], g_f6[b * 2 + 1]);

    // stage this tile's 512 gt bytes in smem (coalesced 512B read)
    __shared__ unsigned int s_sv[128];
    if (tid < 128)
        s_sv[tid] = g_sv32[((size_t)b * SEQ_L >> 2) + p * 128 + tid];
    __syncthreads();
    const unsigned char* sv = (const unsigned char*)s_sv;

    uint4* obase = out + (size_t)b * (SEQ_L * 2) + (size_t)p * 1024;

#pragma unroll
    for (int k = 0; k < 4; ++k) {
        const int slot = tid + k * TPB;      // 0..1023
        const int tl   = slot >> 1;          // local element 0..511
        const int half = slot & 1;
        const int t    = p * 512 + tl;       // global element index

        const int v = (int)sv[tl];
        unsigned bits;
        if (v >= 4 && v <= 6) {
            const int pe = min(t + 1, SEQ_L - 1);
            bits = (F5 > pe) ? B_NO_TS : ((F6 > pe) ? B_NO_TP : B_FULL);
        } else {
            bits = base_bits(v);
        }
        const uint4 val = expand4(bits >> (half * 4));
        __stcs(obase + slot, val);           // streaming: don't pollute L2
    }
}

extern "C" void kernel_launch(void* const* d_in, const int* in_sizes, int n_in,
                              void* d_out, int out_size) {
    const int* in = (const int*)d_in[0];
    uint4* out = (uint4*)d_out;   // float32 output: 8 floats per (b,t)
    gather_kernel<<<NBATCH * 2, TPB>>>(in);
    expand_kernel<<<NBATCH * 4, TPB>>>(out);
}

// round 5
// speedup vs baseline: 1.1857x; 1.1857x over previous
#include <cuda_runtime.h>
#include <cstdint>

// Problem constants
#define SEQ_L   2048      // SEQ_LEN - 1
#define NFEAT   11
#define NBATCH  1024
#define TPB     256
#define EPT     (SEQ_L / TPB)        // 8 elements per thread (pass 1)
#define SPT     (SEQ_L * 2 / TPB)    // 16 uint4 output slots per thread (pass 2)

// Mask rows as 8-bit masks, bit i = mask element i.
//  0:[0,1,0,0,0,0,0,0]=0x02  1:[0,1,1,0,0,0,0,0]=0x06  2:[0,0,0,0,1,0,0,0]=0x10
//  3:[0,0,0,1,1,1,1,1]=0xF8  7:[0,0,0,0,0,0,0,1]=0x80  4,5,6,8 = 0
#define B_FULL  0xF8u
#define B_NO_TS 0x20u
#define B_NO_TP 0x40u

__device__ __forceinline__ unsigned base_bits(int v) {
    unsigned b = 0u;
    b = (v == 0) ? 0x02u : b;
    b = (v == 1) ? 0x06u : b;
    b = (v == 2) ? 0x10u : b;
    b = (v == 3) ? 0xF8u : b;
    b = (v == 7) ? 0x80u : b;
    return b;
}

__global__ __launch_bounds__(TPB)
void mask_type_prob_kernel(const int* __restrict__ in,
                           uint4* __restrict__ out) {
    const int b   = blockIdx.x;
    const int tid = threadIdx.x;

    __shared__ unsigned char sbits[SEQ_L];  // resolved 8-bit mask per element
    __shared__ uint4 lut[16];               // nibble -> 4 floats (0.0/1.0)
    __shared__ int s5[TPB / 32];
    __shared__ int s6[TPB / 32];

    // build nibble LUT (16 threads, before any sync)
    if (tid < 16) {
        uint4 r;
        r.x = (tid & 1u) ? 0x3F800000u : 0u;
        r.y = (tid & 2u) ? 0x3F800000u : 0u;
        r.z = (tid & 4u) ? 0x3F800000u : 0u;
        r.w = (tid & 8u) ? 0x3F800000u : 0u;
        lut[tid] = r;
    }

    const int* row = in + (size_t)b * SEQ_L * NFEAT;

    // ---- Pass 1: strided gather of gt, first occurrence of 5 / 6 ----
    int g[EPT];
    int f5 = SEQ_L;   // sentinel: "never", > any prefix end
    int f6 = SEQ_L;

#pragma unroll
    for (int k = 0; k < EPT; ++k) {
        const int t = tid + k * TPB;
        const int v = __ldcs(row + (size_t)t * NFEAT);   // streaming: no reuse
        g[k] = v;
        if (v == 5) f5 = min(f5, t);
        if (v == 6) f6 = min(f6, t);
    }

#pragma unroll
    for (int off = 16; off > 0; off >>= 1) {
        f5 = min(f5, __shfl_down_sync(0xFFFFFFFFu, f5, off));
        f6 = min(f6, __shfl_down_sync(0xFFFFFFFFu, f6, off));
    }
    const int lane = tid & 31;
    const int wid  = tid >> 5;
    if (lane == 0) { s5[wid] = f5; s6[wid] = f6; }
    __syncthreads();

    int F5 = SEQ_L, F6 = SEQ_L;
#pragma unroll
    for (int i = 0; i < TPB / 32; ++i) {
        F5 = min(F5, s5[i]);
        F6 = min(F6, s6[i]);
    }

    // ---- Pass 1.5: resolve final mask bits per element (once), to smem ----
#pragma unroll
    for (int k = 0; k < EPT; ++k) {
        const int t = tid + k * TPB;
        const int v = g[k];
        unsigned bits;
        if (v >= 4 && v <= 6) {
            // cumsum==0 over prefix [0, pe]  <=>  first occurrence > pe
            const int pe = min(t + 1, SEQ_L - 1);
            bits = (F5 > pe) ? B_NO_TS : ((F6 > pe) ? B_NO_TP : B_FULL);
        } else {
            const int c = v < 0 ? 0 : (v > 8 ? 8 : v);
            bits = base_bits(c);
        }
        sbits[t] = (unsigned char)bits;
    }
    __syncthreads();

    // ---- Pass 2: slot-mapped coalesced stores, LUT expansion ----
    // 4096 uint4 slots per row; slot s -> element s>>1, half s&1.
    // half = tid&1 is constant per thread -> fixed nibble shift.
    uint4* orow = out + (size_t)b * (SEQ_L * 2);
    const int sh = (tid & 1) * 4;

#pragma unroll
    for (int k = 0; k < SPT; ++k) {
        const int slot = tid + k * TPB;
        const unsigned byte = sbits[slot >> 1];
        const uint4 val = lut[(byte >> sh) & 0xFu];
        __stcs(orow + slot, val);            // streaming store
    }
}

extern "C" void kernel_launch(void* const* d_in, const int* in_sizes, int n_in,
                              void* d_out, int out_size) {
    const int* in = (const int*)d_in[0];
    uint4* out = (uint4*)d_out;   // float32 output: 8 floats per (b,t)
    mask_type_prob_kernel<<<NBATCH, TPB>>>(in, out);
}

// round 6
// speedup vs baseline: 1.2051x; 1.0164x over previous
#include <cuda_runtime.h>
#include <cstdint>

// Problem constants
#define SEQ_L   2048      // SEQ_LEN - 1
#define NFEAT   11
#define NBATCH  1024
#define TPB     256
#define HALF    (SEQ_L / 2)          // 1024 elements per CTA
#define EPT     (HALF / TPB)         // 4 gathered elements per thread
#define SPT     (HALF * 2 / TPB)     // 8 uint4 output slots per thread

// Mask rows as 8-bit masks, bit i = mask element i.
//  0:[0,1,0,0,0,0,0,0]=0x02  1:[0,1,1,0,0,0,0,0]=0x06  2:[0,0,0,0,1,0,0,0]=0x10
//  3:[0,0,0,1,1,1,1,1]=0xF8  7:[0,0,0,0,0,0,0,1]=0x80  4,5,6,8 = 0
#define B_FULL  0xF8u
#define B_NO_TS 0x20u
#define B_NO_TP 0x40u

__device__ __forceinline__ unsigned base_bits(int v) {
    unsigned b = 0u;
    b = (v == 0) ? 0x02u : b;
    b = (v == 1) ? 0x06u : b;
    b = (v == 2) ? 0x10u : b;
    b = (v == 3) ? 0xF8u : b;
    b = (v == 7) ? 0x80u : b;
    return b;
}

__device__ __forceinline__ uint32_t smem_u32(const void* p) {
    uint32_t a;
    asm("{ .reg .u64 t; cvta.to.shared.u64 t, %1; cvt.u32.u64 %0, t; }"
        : "=r"(a) : "l"(p));
    return a;
}

__device__ __forceinline__ int dsmem_ld_s32(uint32_t local_addr, uint32_t rank) {
    uint32_t remote; int v;
    asm volatile("mapa.shared::cluster.u32 %0, %1, %2;"
                 : "=r"(remote) : "r"(local_addr), "r"(rank));
    asm volatile("ld.shared::cluster.s32 %0, [%1];" : "=r"(v) : "r"(remote));
    return v;
}

__global__ __launch_bounds__(TPB) __cluster_dims__(2, 1, 1)
void mask_type_prob_kernel(const int* __restrict__ in,
                           uint4* __restrict__ out) {
    const int b   = blockIdx.x >> 1;
    const int h   = blockIdx.x & 1;     // which half of the row
    const int tid = threadIdx.x;

    __shared__ unsigned char sbits[HALF];  // resolved mask byte per element
    __shared__ uint4 lut[16];              // nibble -> 4 floats
    __shared__ int sF[2];                  // this CTA's local (f5, f6)
    __shared__ int s5[TPB / 32];
    __shared__ int s6[TPB / 32];

    if (tid < 16) {
        uint4 r;
        r.x = (tid & 1u) ? 0x3F800000u : 0u;
        r.y = (tid & 2u) ? 0x3F800000u : 0u;
        r.z = (tid & 4u) ? 0x3F800000u : 0u;
        r.w = (tid & 8u) ? 0x3F800000u : 0u;
        lut[tid] = r;
    }

    const int tbase = h * HALF;
    const int* row = in + (size_t)b * SEQ_L * NFEAT;

    // ---- Pass 1: gather this half's gt values, local first occurrence ----
    int g[EPT];
    int f5 = SEQ_L, f6 = SEQ_L;   // sentinel "never"

#pragma unroll
    for (int k = 0; k < EPT; ++k) {
        const int t = tbase + tid + k * TPB;
        const int v = __ldcs(row + (size_t)t * NFEAT);
        g[k] = v;
        if (v == 5) f5 = min(f5, t);
        if (v == 6) f6 = min(f6, t);
    }

#pragma unroll
    for (int off = 16; off > 0; off >>= 1) {
        f5 = min(f5, __shfl_down_sync(0xFFFFFFFFu, f5, off));
        f6 = min(f6, __shfl_down_sync(0xFFFFFFFFu, f6, off));
    }
    const int lane = tid & 31;
    const int wid  = tid >> 5;
    if (lane == 0) { s5[wid] = f5; s6[wid] = f6; }
    __syncthreads();
    if (tid == 0) {
        int F5l = SEQ_L, F6l = SEQ_L;
#pragma unroll
        for (int i = 0; i < TPB / 32; ++i) {
            F5l = min(F5l, s5[i]);
            F6l = min(F6l, s6[i]);
        }
        sF[0] = F5l;
        sF[1] = F6l;
    }

    // ---- Cluster exchange: combine halves' minima ----
    // sync #1: partner's sF is written before we read it (block-wide barrier too)
    asm volatile("barrier.cluster.arrive.aligned;" ::: "memory");
    asm volatile("barrier.cluster.wait.aligned;" ::: "memory");

    const uint32_t peer = (uint32_t)(h ^ 1);
    const uint32_t sF_addr = smem_u32(sF);
    const int F5 = min(sF[0], dsmem_ld_s32(sF_addr,     peer));
    const int F6 = min(sF[1], dsmem_ld_s32(sF_addr + 4, peer));

    // sync #2: our smem must stay alive until the peer has read it
    asm volatile("barrier.cluster.arrive.aligned;" ::: "memory");
    asm volatile("barrier.cluster.wait.aligned;" ::: "memory");

    // ---- Pass 1.5: resolve final mask byte per element (values in regs) ----
#pragma unroll
    for (int k = 0; k < EPT; ++k) {
        const int tl = tid + k * TPB;      // local index in this half
        const int t  = tbase + tl;
        const int v  = g[k];
        unsigned bits;
        if (v >= 4 && v <= 6) {
            // cumsum==0 over prefix [0, pe]  <=>  first occurrence > pe
            const int pe = min(t + 1, SEQ_L - 1);
            bits = (F5 > pe) ? B_NO_TS : ((F6 > pe) ? B_NO_TP : B_FULL);
        } else {
            const int c = v < 0 ? 0 : (v > 8 ? 8 : v);
            bits = base_bits(c);
        }
        sbits[tl] = (unsigned char)bits;
    }
    __syncthreads();

    // ---- Pass 2: slot-mapped coalesced streaming stores ----
    // This half's output: 1024 elements * 2 uint4 = 2048 slots.
    uint4* orow = out + (size_t)b * (SEQ_L * 2) + (size_t)h * (HALF * 2);
    const int sh = (tid & 1) * 4;

#pragma unroll
    for (int k = 0; k < SPT; ++k) {
        const int slot = tid + k * TPB;
        const unsigned byte = sbits[slot >> 1];
        const uint4 val = lut[(byte >> sh) & 0xFu];
        __stcs(orow + slot, val);
    }
}

extern "C" void kernel_launch(void* const* d_in, const int* in_sizes, int n_in,
                              void* d_out, int out_size) {
    const int* in = (const int*)d_in[0];
    uint4* out = (uint4*)d_out;   // float32 output: 8 floats per (b,t)
    mask_type_prob_kernel<<<NBATCH * 2, TPB>>>(in, out);
}